// round 15
// baseline (speedup 1.0000x reference)
#include <cuda_runtime.h>
#include <cuda_bf16.h>
#include <cstdint>
#include <math.h>

// Problem constants
#define Hq    12
#define HKV   2
#define NG    6          // Hq / HKV
#define Dh    128
#define HID   1536
#define Bc    4
#define Sc    2048
#define Tn    (Bc*Sc)    // 8192 tokens
#define NQKV  2048       // Hq*Dh + 2*HKV*Dh
#define NSLOTS 16384
#define OUT_ELEMS   ((size_t)Tn*HID)          // 12582912
#define CACHE_ELEMS ((size_t)NSLOTS*HKV*Dh)   // 4194304

// Scratch (device globals; no runtime allocation allowed)
__device__ float g_qkv[(size_t)Tn * NQKV];    // 67 MB
__device__ float g_attn[(size_t)Tn * HID];    // 50 MB (tf32-rounded by attn)
__device__ float g_x [(size_t)Tn * HID];      // tf32-rounded x
__device__ float g_w1[(size_t)NQKV * HID];    // tf32-rounded Wqkv
__device__ float g_w2[(size_t)HID * HID];     // tf32-rounded Wo

// ===========================================================================
// Helpers (portable to plain sm_103 target)
// ===========================================================================
__device__ __forceinline__ float to_tf32(float x) {
    float y;
    asm("cvt.rna.tf32.f32 %0, %1;" : "=f"(y) : "f"(x));
    return y;
}

__device__ __forceinline__ uint32_t smem_u32(const void* p) {
    uint32_t a;
    asm("{ .reg .u64 t; cvta.to.shared.u64 t, %1; cvt.u32.u64 %0, t; }"
        : "=r"(a) : "l"(p));
    return a;
}

__device__ __forceinline__ void cp_async16(uint32_t saddr, const void* g) {
    asm volatile("cp.async.cg.shared.global [%0], [%1], 16;"
                 :: "r"(saddr), "l"(g) : "memory");
}

__device__ __forceinline__ void mma_tf32_16x8x8(
    float& d0, float& d1, float& d2, float& d3,
    float a0, float a1, float a2, float a3,
    float b0, float b1)
{
    uint32_t A0 = __float_as_uint(a0), A1 = __float_as_uint(a1);
    uint32_t A2 = __float_as_uint(a2), A3 = __float_as_uint(a3);
    uint32_t B0 = __float_as_uint(b0), B1 = __float_as_uint(b1);
    asm volatile(
        "mma.sync.aligned.m16n8k8.row.col.f32.tf32.tf32.f32 "
        "{%0,%1,%2,%3}, {%4,%5,%6,%7}, {%8,%9}, {%0,%1,%2,%3};"
        : "+f"(d0), "+f"(d1), "+f"(d2), "+f"(d3)
        : "r"(A0), "r"(A1), "r"(A2), "r"(A3), "r"(B0), "r"(B1));
}

// ---------------------------------------------------------------------------
// Pre-pass: round fp32 buffer to tf32 (rna) into scratch.
// ---------------------------------------------------------------------------
__global__ void tf32_round_kernel(const float* __restrict__ in,
                                  float* __restrict__ out, int n4) {
    const int i = blockIdx.x * blockDim.x + threadIdx.x;
    if (i < n4) {
        float4 v = ((const float4*)in)[i];
        v.x = to_tf32(v.x); v.y = to_tf32(v.y);
        v.z = to_tf32(v.z); v.w = to_tf32(v.w);
        ((float4*)out)[i] = v;
    }
}

// ===========================================================================
// TF32 tensor-core GEMM: 128x128 tile, 4 warps (2Mx2N), 64x64 warp tile,
// 3-stage cp.async ring with ONE __syncthreads per chunk (CUTLASS multistage
// schedule), stride-36 fragment layout. Smem 110.6 KB -> 2 CTAs/SM.
// M,N mult of 128, K mult of 32 (and K >= 64).
// ===========================================================================
#define GSTR 36
#define GBUF (128 * GSTR)
#define G_STAGES 3
#define G_SMEM_FLOATS (2 * G_STAGES * GBUF)     // A[3] | B[3] = 110592 B

__global__ __launch_bounds__(128, 2) void gemm_mma_kernel(
    const float* __restrict__ A, const float* __restrict__ Bw,
    const float* __restrict__ bias, float* __restrict__ C,
    int M, int N, int K)
{
    extern __shared__ float smem[];
    const uint32_t sbase = smem_u32(smem);

    const int tid  = threadIdx.x;
    const int wid  = tid >> 5;
    const int lane = tid & 31;
    const int gid  = lane >> 2;
    const int tig  = lane & 3;

    const int m0 = blockIdx.y * 128;
    const int n0 = blockIdx.x * 128;
    const int wm0 = (wid >> 1) * 64;
    const int wn0 = (wid & 1) * 64;

    float acc[4][8][4];
#pragma unroll
    for (int mi = 0; mi < 4; mi++)
#pragma unroll
        for (int ni = 0; ni < 8; ni++)
#pragma unroll
            for (int r = 0; r < 4; r++) acc[mi][ni][r] = 0.f;

    const int nchunks = K >> 5;

#define GEMM_ISSUE(kc, buf) do {                                              \
    _Pragma("unroll")                                                         \
    for (int i = 0; i < 8; i++) {                                             \
        const int idx = tid + i * 128;                                        \
        const int r  = idx >> 3;                                              \
        const int cg = (idx & 7) << 2;                                        \
        cp_async16(sbase + (uint32_t)(((buf) * GBUF + r * GSTR + cg) * 4),    \
                   A + (size_t)(m0 + r) * K + (kc) + cg);                     \
        cp_async16(sbase + (uint32_t)(((G_STAGES + (buf)) * GBUF + r * GSTR + cg) * 4),\
                   Bw + (size_t)(n0 + r) * K + (kc) + cg);                    \
    }                                                                         \
    asm volatile("cp.async.commit_group;" ::: "memory");                      \
} while (0)

    // prologue: prefetch chunks 0 and 1
    GEMM_ISSUE(0, 0);
    GEMM_ISSUE(32, 1);

    int buf = 0;
    for (int c = 0; c < nchunks; c++) {
        // chunk c must be complete before compute; groups c..min(c+1,n-1)
        // are outstanding at this point.
        if (c + 1 < nchunks) {
            asm volatile("cp.async.wait_group 1;" ::: "memory");
        } else {
            asm volatile("cp.async.wait_group 0;" ::: "memory");
        }
        __syncthreads();   // (a) group-c data visible to all warps
                           // (b) all warps finished compute(c-1) -> buffer
                           //     (c+2)%3 == (c-1)%3 is free to refill

        if (c + 2 < nchunks) {
            const int nb = (buf + 2 >= G_STAGES) ? buf + 2 - G_STAGES : buf + 2;
            GEMM_ISSUE((c + 2) << 5, nb);
        }

        const float* Ab = smem + buf * GBUF;
        const float* Bb = smem + (G_STAGES + buf) * GBUF;
#pragma unroll
        for (int ks = 0; ks < 4; ks++) {
            const int kk = ks * 8;
            float afr[4][4];
#pragma unroll
            for (int mi = 0; mi < 4; mi++) {
                const int r = wm0 + mi * 16 + gid;
                const int cA = kk + tig;
                afr[mi][0] = Ab[r * GSTR + cA];
                afr[mi][1] = Ab[(r + 8) * GSTR + cA];
                afr[mi][2] = Ab[r * GSTR + cA + 4];
                afr[mi][3] = Ab[(r + 8) * GSTR + cA + 4];
            }
            float bfr[8][2];
#pragma unroll
            for (int ni = 0; ni < 8; ni++) {
                const int rB = wn0 + ni * 8 + gid;
                const int cB = kk + tig;
                bfr[ni][0] = Bb[rB * GSTR + cB];
                bfr[ni][1] = Bb[rB * GSTR + cB + 4];
            }
#pragma unroll
            for (int ni = 0; ni < 8; ni++) {
#pragma unroll
                for (int mi = 0; mi < 4; mi++) {
                    mma_tf32_16x8x8(acc[mi][ni][0], acc[mi][ni][1],
                                    acc[mi][ni][2], acc[mi][ni][3],
                                    afr[mi][0], afr[mi][1], afr[mi][2], afr[mi][3],
                                    bfr[ni][0], bfr[ni][1]);
                }
            }
        }
        buf = (buf + 1 >= G_STAGES) ? 0 : buf + 1;
    }

#pragma unroll
    for (int mi = 0; mi < 4; mi++) {
        const int row = m0 + wm0 + mi * 16 + gid;
#pragma unroll
        for (int ni = 0; ni < 8; ni++) {
            const int col = n0 + wn0 + ni * 8 + 2 * tig;
            float b0 = 0.f, b1 = 0.f;
            if (bias) { b0 = bias[col]; b1 = bias[col + 1]; }
            float2 v0 = make_float2(acc[mi][ni][0] + b0, acc[mi][ni][1] + b1);
            float2 v1 = make_float2(acc[mi][ni][2] + b0, acc[mi][ni][3] + b1);
            *(float2*)(C + (size_t)row * N + col)       = v0;
            *(float2*)(C + (size_t)(row + 8) * N + col) = v1;
        }
    }
}

// ---------------------------------------------------------------------------
// RoPE (in place on g_qkv) + scatter EXACT rotated k and raw v to caches,
// and round q/k/v in qkv to tf32 (so attention loads need no cvt).
// ---------------------------------------------------------------------------
__global__ void rope_scatter_kernel(float* __restrict__ qkv,
                                    const float* __restrict__ cosb,
                                    const float* __restrict__ sinb,
                                    const int* __restrict__ slot,
                                    float* __restrict__ kc,
                                    float* __restrict__ vc) {
    const int r = blockIdx.x;
    float* row = qkv + (size_t)r * NQKV;
    const float* cr = cosb + (size_t)r * Dh;
    const float* sr = sinb + (size_t)r * Dh;
    const int s = slot[r];

    for (int idx = threadIdx.x; idx < 14 * 64; idx += blockDim.x) {
        const int head = idx >> 6;
        const int d = idx & 63;
        float* hp = row + head * Dh;
        const float x1 = hp[d], x2 = hp[d + 64];
        const float c1 = cr[d], s1 = sr[d];
        const float c2 = cr[d + 64], s2 = sr[d + 64];
        const float o1 = x1 * c1 - x2 * s1;
        const float o2 = x2 * c2 + x1 * s2;
        hp[d]      = to_tf32(o1);
        hp[d + 64] = to_tf32(o2);
        if (head >= Hq) {
            const int kh = head - Hq;
            float* kdst = kc + ((size_t)s * HKV + kh) * Dh;
            kdst[d]      = o1;        // cache keeps exact values
            kdst[d + 64] = o2;
        }
    }
    for (int idx = threadIdx.x; idx < HKV * Dh; idx += blockDim.x) {
        const float v = row[Hq * Dh + HKV * Dh + idx];
        vc[(size_t)s * (HKV * Dh) + idx] = v;         // exact
        row[Hq * Dh + HKV * Dh + idx] = to_tf32(v);   // rounded for PV mma
    }
}

// ===========================================================================
// Tensor-core causal GQA flash attention (tf32 mma.sync), cp.async-pipelined.
// R14-validated: 8 warps (4M x 2N), m32 warp tiles, exp2f softmax with
// log2e-folded scale.
// ===========================================================================
#define AQSTR 132
#define AKSTR 132
#define AVSTR 136
#define ASSTR 68
#define ATT_Q_FL   (128 * AQSTR)
#define ATT_K_FL   (64 * AKSTR)
#define ATT_V_FL   (64 * AVSTR)
#define ATT_S_FL   (128 * ASSTR)
#define ATT2_SMEM_FLOATS (ATT_Q_FL + 2 * ATT_K_FL + ATT_V_FL + ATT_S_FL + 3 * 128)

__global__ __launch_bounds__(256, 1) void attn_mma_kernel(
    const float* __restrict__ qkv, float* __restrict__ out)
{
    extern __shared__ float sm[];
    float* Qs = sm;
    float* Ks0 = Qs + ATT_Q_FL;                 // [2][64][AKSTR]
    float* Vs  = Ks0 + 2 * ATT_K_FL;
    float* Ss  = Vs + ATT_V_FL;
    float* mrow = Ss + ATT_S_FL;
    float* lrow = mrow + 128;
    float* arow = lrow + 128;

    const uint32_t sbase = smem_u32(sm);
    const uint32_t ks_s0 = sbase + (uint32_t)(ATT_Q_FL * 4);
    const uint32_t vs_s  = sbase + (uint32_t)((ATT_Q_FL + 2 * ATT_K_FL) * 4);

    const int qt = (gridDim.x - 1) - blockIdx.x;   // heavy tiles first
    const int h = blockIdx.y, b = blockIdx.z;
    const int kh = h / NG;
    const int tid = threadIdx.x;
    const int wid = tid >> 5;
    const int lane = tid & 31;
    const int gid = lane >> 2;
    const int tig = lane & 3;
    const int wm = wid >> 1;          // 0..3 -> 32-row strip
    const int wn = wid & 1;           // 0..1
    const int q0 = qt * 128;
    const int rowbase = b * Sc;
    // scores scaled by (1/sqrt(128)) * log2(e); softmax uses exp2f.
    const float scale = 0.08838834764831845f * 1.44269504088896340736f;

#define ATT_ISSUE_K(kt_, buf_) do {                                           \
    const uint32_t kb_ = ks_s0 + (uint32_t)((buf_) * ATT_K_FL * 4);           \
    for (int i_ = tid; i_ < 64 * 32; i_ += 256) {                             \
        const int r_ = i_ >> 5; const int c_ = (i_ & 31) << 2;                \
        cp_async16(kb_ + (uint32_t)((r_ * AKSTR + c_) * 4),                   \
                   qkv + (size_t)(rowbase + (kt_) * 64 + r_) * NQKV           \
                       + Hq * Dh + kh * Dh + c_);                             \
    }                                                                         \
} while (0)

#define ATT_ISSUE_V(kt_) do {                                                 \
    for (int i_ = tid; i_ < 64 * 32; i_ += 256) {                             \
        const int r_ = i_ >> 5; const int c_ = (i_ & 31) << 2;                \
        cp_async16(vs_s + (uint32_t)((r_ * AVSTR + c_) * 4),                  \
                   qkv + (size_t)(rowbase + (kt_) * 64 + r_) * NQKV           \
                       + Hq * Dh + HKV * Dh + kh * Dh + c_);                  \
    }                                                                         \
} while (0)

    // --- prologue: prefetch K tile 0, load Q, init stats ---
    ATT_ISSUE_K(0, 0);
    asm volatile("cp.async.commit_group;" ::: "memory");

    for (int i = tid; i < 128 * 32; i += 256) {
        const int r = i >> 5;
        const int col = (i & 31) << 2;
        float4 v = *(const float4*)(qkv + (size_t)(rowbase + q0 + r) * NQKV + h * Dh + col);
        *(float4*)(Qs + r * AQSTR + col) = v;
    }
    if (tid < 128) { mrow[tid] = -1e30f; lrow[tid] = 0.f; }

    float oacc[2][8][4];
#pragma unroll
    for (int mi = 0; mi < 2; mi++)
#pragma unroll
        for (int nt = 0; nt < 8; nt++)
#pragma unroll
            for (int r = 0; r < 4; r++) oacc[mi][nt][r] = 0.f;

    asm volatile("cp.async.wait_group 0;" ::: "memory");
    __syncthreads();    // K0 + Q + stats visible

    const int nkt = 2 * qt + 2;
    for (int kt = 0; kt < nkt; kt++) {
        const int k0 = kt * 64;
        const int buf = kt & 1;

        // --- issue V(kt) and prefetch K(kt+1); one commit group ---
        ATT_ISSUE_V(kt);
        if (kt + 1 < nkt) ATT_ISSUE_K(kt + 1, buf ^ 1);
        asm volatile("cp.async.commit_group;" ::: "memory");

        // --- QK^T from Ks[buf]: warp m32 x n32, k=128 ---
        const float* Kb = Ks0 + buf * ATT_K_FL;
        float sacc[2][4][4];
#pragma unroll
        for (int mi = 0; mi < 2; mi++)
#pragma unroll
            for (int nt = 0; nt < 4; nt++)
#pragma unroll
                for (int r = 0; r < 4; r++) sacc[mi][nt][r] = 0.f;

#pragma unroll
        for (int kk = 0; kk < 16; kk++) {
            const int kc = kk * 8;
            float afr[2][4];
#pragma unroll
            for (int mi = 0; mi < 2; mi++) {
                const int rA = wm * 32 + mi * 16 + gid;
                afr[mi][0] = Qs[rA * AQSTR + kc + tig];
                afr[mi][1] = Qs[(rA + 8) * AQSTR + kc + tig];
                afr[mi][2] = Qs[rA * AQSTR + kc + tig + 4];
                afr[mi][3] = Qs[(rA + 8) * AQSTR + kc + tig + 4];
            }
#pragma unroll
            for (int nt = 0; nt < 4; nt++) {
                const int rB = wn * 32 + nt * 8 + gid;
                const float b0 = Kb[rB * AKSTR + kc + tig];
                const float b1 = Kb[rB * AKSTR + kc + tig + 4];
#pragma unroll
                for (int mi = 0; mi < 2; mi++) {
                    mma_tf32_16x8x8(sacc[mi][nt][0], sacc[mi][nt][1],
                                    sacc[mi][nt][2], sacc[mi][nt][3],
                                    afr[mi][0], afr[mi][1], afr[mi][2], afr[mi][3],
                                    b0, b1);
                }
            }
        }

        // --- scale(+log2e) + causal mask + write scores ---
#pragma unroll
        for (int mi = 0; mi < 2; mi++) {
            const int r0 = wm * 32 + mi * 16 + gid;
            const int r1 = r0 + 8;
            const int qr0 = q0 + r0, qr1 = q0 + r1;
#pragma unroll
            for (int nt = 0; nt < 4; nt++) {
                const int col = wn * 32 + nt * 8 + 2 * tig;
                const int gc = k0 + col;
                Ss[r0 * ASSTR + col]     = (gc     <= qr0) ? sacc[mi][nt][0] * scale : -1e30f;
                Ss[r0 * ASSTR + col + 1] = (gc + 1 <= qr0) ? sacc[mi][nt][1] * scale : -1e30f;
                Ss[r1 * ASSTR + col]     = (gc     <= qr1) ? sacc[mi][nt][2] * scale : -1e30f;
                Ss[r1 * ASSTR + col + 1] = (gc + 1 <= qr1) ? sacc[mi][nt][3] * scale : -1e30f;
            }
        }
        __syncthreads();

        // --- online softmax (base-2): 2 threads/row, interleaved chunks ---
        {
            const int row = tid >> 1;
            const int part = tid & 1;
            float* sp = Ss + row * ASSTR + part * 4;   // chunks at 8j + 4*part
            float4 v[8];
#pragma unroll
            for (int j = 0; j < 8; j++) v[j] = *(float4*)(sp + j * 8);
            float mx = -1e30f;
#pragma unroll
            for (int j = 0; j < 8; j++)
                mx = fmaxf(mx, fmaxf(fmaxf(v[j].x, v[j].y), fmaxf(v[j].z, v[j].w)));
            mx = fmaxf(mx, __shfl_xor_sync(0xFFFFFFFFu, mx, 1));
            const float mo = mrow[row];
            const float mn = fmaxf(mo, mx);
            const float alpha = exp2f(mo - mn);
            float s = 0.f;
#pragma unroll
            for (int j = 0; j < 8; j++) {
                v[j].x = exp2f(v[j].x - mn); v[j].y = exp2f(v[j].y - mn);
                v[j].z = exp2f(v[j].z - mn); v[j].w = exp2f(v[j].w - mn);
                s += (v[j].x + v[j].y) + (v[j].z + v[j].w);
            }
#pragma unroll
            for (int j = 0; j < 8; j++) {
                v[j].x = to_tf32(v[j].x); v[j].y = to_tf32(v[j].y);
                v[j].z = to_tf32(v[j].z); v[j].w = to_tf32(v[j].w);
                *(float4*)(sp + j * 8) = v[j];
            }
            s += __shfl_xor_sync(0xFFFFFFFFu, s, 1);
            if (part == 0) {
                mrow[row] = mn;
                lrow[row] = lrow[row] * alpha + s;
                arow[row] = alpha;
            }
        }
        // V(kt) [+K(kt+1)] must have landed; publish with the softmax barrier
        asm volatile("cp.async.wait_group 0;" ::: "memory");
        __syncthreads();

        // --- rescale O accumulators and P @ V (warp m32 x n64) ---
        {
            float al[2][2];
#pragma unroll
            for (int mi = 0; mi < 2; mi++) {
                al[mi][0] = arow[wm * 32 + mi * 16 + gid];
                al[mi][1] = arow[wm * 32 + mi * 16 + gid + 8];
            }
#pragma unroll
            for (int mi = 0; mi < 2; mi++)
#pragma unroll
                for (int nt = 0; nt < 8; nt++) {
                    oacc[mi][nt][0] *= al[mi][0]; oacc[mi][nt][1] *= al[mi][0];
                    oacc[mi][nt][2] *= al[mi][1]; oacc[mi][nt][3] *= al[mi][1];
                }
#pragma unroll
            for (int ks = 0; ks < 8; ks++) {
                const int kc = ks * 8;
                float pfr[2][4];
#pragma unroll
                for (int mi = 0; mi < 2; mi++) {
                    const int rA = wm * 32 + mi * 16 + gid;
                    pfr[mi][0] = Ss[rA * ASSTR + kc + tig];
                    pfr[mi][1] = Ss[(rA + 8) * ASSTR + kc + tig];
                    pfr[mi][2] = Ss[rA * ASSTR + kc + tig + 4];
                    pfr[mi][3] = Ss[(rA + 8) * ASSTR + kc + tig + 4];
                }
#pragma unroll
                for (int nt = 0; nt < 8; nt++) {
                    const int n0 = wn * 64 + nt * 8;
                    const float b0 = Vs[(kc + tig) * AVSTR + n0 + gid];
                    const float b1 = Vs[(kc + tig + 4) * AVSTR + n0 + gid];
#pragma unroll
                    for (int mi = 0; mi < 2; mi++) {
                        mma_tf32_16x8x8(oacc[mi][nt][0], oacc[mi][nt][1],
                                        oacc[mi][nt][2], oacc[mi][nt][3],
                                        pfr[mi][0], pfr[mi][1], pfr[mi][2], pfr[mi][3],
                                        b0, b1);
                    }
                }
            }
        }
        __syncthreads();   // protect Vs/Ss before next iteration's overwrite
    }

    // --- normalize + write out (tf32-rounded for the out-projection) ---
#pragma unroll
    for (int mi = 0; mi < 2; mi++) {
        const int r0 = wm * 32 + mi * 16 + gid;
        const int r1 = r0 + 8;
        const float inv0 = 1.0f / lrow[r0];
        const float inv1 = 1.0f / lrow[r1];
        const size_t ob0 = (size_t)(rowbase + q0 + r0) * HID + h * Dh;
        const size_t ob1 = (size_t)(rowbase + q0 + r1) * HID + h * Dh;
#pragma unroll
        for (int nt = 0; nt < 8; nt++) {
            const int col = wn * 64 + nt * 8 + 2 * tig;
            *(float2*)(out + ob0 + col) =
                make_float2(to_tf32(oacc[mi][nt][0] * inv0), to_tf32(oacc[mi][nt][1] * inv0));
            *(float2*)(out + ob1 + col) =
                make_float2(to_tf32(oacc[mi][nt][2] * inv1), to_tf32(oacc[mi][nt][3] * inv1));
        }
    }
}

// ---------------------------------------------------------------------------
// kernel_launch
// ---------------------------------------------------------------------------
extern "C" void kernel_launch(void* const* d_in, const int* in_sizes, int n_in,
                              void* d_out, int out_size) {
    const float* x    = (const float*)d_in[0];
    const float* cosb = (const float*)d_in[1];
    const float* sinb = (const float*)d_in[2];
    const float* kci  = (const float*)d_in[3];
    const float* vci  = (const float*)d_in[4];
    const int*   slot = (const int*)d_in[5];
    const float* Wqkv = (const float*)d_in[6];
    const float* bqkv = (const float*)d_in[7];
    const float* Wo   = (const float*)d_in[8];

    float* out = (float*)d_out;
    float* kc  = out + OUT_ELEMS;
    float* vc  = kc + CACHE_ELEMS;

    float* qkv;  cudaGetSymbolAddress((void**)&qkv,  g_qkv);
    float* attn; cudaGetSymbolAddress((void**)&attn, g_attn);
    float* xe;   cudaGetSymbolAddress((void**)&xe,   g_x);
    float* w1e;  cudaGetSymbolAddress((void**)&w1e,  g_w1);
    float* w2e;  cudaGetSymbolAddress((void**)&w2e,  g_w2);

    cudaFuncSetAttribute(attn_mma_kernel,
                         cudaFuncAttributeMaxDynamicSharedMemorySize,
                         ATT2_SMEM_FLOATS * (int)sizeof(float));
    cudaFuncSetAttribute(gemm_mma_kernel,
                         cudaFuncAttributeMaxDynamicSharedMemorySize,
                         G_SMEM_FLOATS * (int)sizeof(float));

    // 1. seed caches with the input caches
    cudaMemcpyAsync(kc, kci, CACHE_ELEMS * sizeof(float), cudaMemcpyDeviceToDevice);
    cudaMemcpyAsync(vc, vci, CACHE_ELEMS * sizeof(float), cudaMemcpyDeviceToDevice);

    // 2. tf32 pre-rounding of GEMM operands
    tf32_round_kernel<<<(Tn * HID / 4 + 255) / 256, 256>>>(x,    xe,  Tn * HID / 4);
    tf32_round_kernel<<<(NQKV * HID / 4 + 255) / 256, 256>>>(Wqkv, w1e, NQKV * HID / 4);
    tf32_round_kernel<<<(HID * HID / 4 + 255) / 256, 256>>>(Wo,   w2e, HID * HID / 4);

    // 3. QKV projection (3-stage single-barrier cp.async tf32 mma GEMM)
    {
        dim3 grid(NQKV / 128, Tn / 128);
        gemm_mma_kernel<<<grid, 128, G_SMEM_FLOATS * sizeof(float)>>>(
            xe, w1e, bqkv, qkv, Tn, NQKV, HID);
    }

    // 4. RoPE in place (+tf32 rounding) + exact cache scatter
    rope_scatter_kernel<<<Tn, 256>>>(qkv, cosb, sinb, slot, kc, vc);

    // 5. causal GQA flash attention (8-warp m32-tile cp.async tensor cores)
    {
        dim3 grid(Sc / 128, Hq, Bc);
        attn_mma_kernel<<<grid, 256, ATT2_SMEM_FLOATS * sizeof(float)>>>(qkv, attn);
    }

    // 6. output projection (3-stage single-barrier cp.async tf32 mma GEMM)
    {
        dim3 grid(HID / 128, Tn / 128);
        gemm_mma_kernel<<<grid, 128, G_SMEM_FLOATS * sizeof(float)>>>(
            attn, w2e, nullptr, out, Tn, HID, HID);
    }
}

// round 16
// speedup vs baseline: 1.0356x; 1.0356x over previous
#include <cuda_runtime.h>
#include <cuda_bf16.h>
#include <cstdint>
#include <math.h>

// Problem constants
#define Hq    12
#define HKV   2
#define NG    6          // Hq / HKV
#define Dh    128
#define HID   1536
#define Bc    4
#define Sc    2048
#define Tn    (Bc*Sc)    // 8192 tokens
#define NQKV  2048       // Hq*Dh + 2*HKV*Dh
#define NSLOTS 16384
#define OUT_ELEMS   ((size_t)Tn*HID)          // 12582912
#define CACHE_ELEMS ((size_t)NSLOTS*HKV*Dh)   // 4194304

// Scratch (device globals; no runtime allocation allowed)
__device__ float g_qkv[(size_t)Tn * NQKV];    // 67 MB
__device__ float g_attn[(size_t)Tn * HID];    // 50 MB (tf32-rounded by attn)
__device__ float g_x [(size_t)Tn * HID];      // tf32-rounded x
__device__ float g_w1[(size_t)NQKV * HID];    // tf32-rounded Wqkv
__device__ float g_w2[(size_t)HID * HID];     // tf32-rounded Wo

// ===========================================================================
// Helpers (portable to plain sm_103 target)
// ===========================================================================
__device__ __forceinline__ float to_tf32(float x) {
    float y;
    asm("cvt.rna.tf32.f32 %0, %1;" : "=f"(y) : "f"(x));
    return y;
}

__device__ __forceinline__ uint32_t smem_u32(const void* p) {
    uint32_t a;
    asm("{ .reg .u64 t; cvta.to.shared.u64 t, %1; cvt.u32.u64 %0, t; }"
        : "=r"(a) : "l"(p));
    return a;
}

__device__ __forceinline__ void cp_async16(uint32_t saddr, const void* g) {
    asm volatile("cp.async.cg.shared.global [%0], [%1], 16;"
                 :: "r"(saddr), "l"(g) : "memory");
}

__device__ __forceinline__ void mma_tf32_16x8x8(
    float& d0, float& d1, float& d2, float& d3,
    float a0, float a1, float a2, float a3,
    float b0, float b1)
{
    uint32_t A0 = __float_as_uint(a0), A1 = __float_as_uint(a1);
    uint32_t A2 = __float_as_uint(a2), A3 = __float_as_uint(a3);
    uint32_t B0 = __float_as_uint(b0), B1 = __float_as_uint(b1);
    asm volatile(
        "mma.sync.aligned.m16n8k8.row.col.f32.tf32.tf32.f32 "
        "{%0,%1,%2,%3}, {%4,%5,%6,%7}, {%8,%9}, {%0,%1,%2,%3};"
        : "+f"(d0), "+f"(d1), "+f"(d2), "+f"(d3)
        : "r"(A0), "r"(A1), "r"(A2), "r"(A3), "r"(B0), "r"(B1));
}

// ---------------------------------------------------------------------------
// Pre-pass: round fp32 buffer to tf32 (rna) into scratch.
// ---------------------------------------------------------------------------
__global__ void tf32_round_kernel(const float* __restrict__ in,
                                  float* __restrict__ out, int n4) {
    const int i = blockIdx.x * blockDim.x + threadIdx.x;
    if (i < n4) {
        float4 v = ((const float4*)in)[i];
        v.x = to_tf32(v.x); v.y = to_tf32(v.y);
        v.z = to_tf32(v.z); v.w = to_tf32(v.w);
        ((float4*)out)[i] = v;
    }
}

// ===========================================================================
// TF32 tensor-core GEMM (R14-validated, best measured): 128x128 tile, 4 warps
// (2Mx2N), 64x64 warp tile, 2-stage cp.async ring, stride-36 fragments.
// ===========================================================================
#define GSTR 36
#define GBUF (128 * GSTR)
#define G_SMEM_FLOATS (4 * GBUF)                // A[2] | B[2] = 73728 B

__global__ __launch_bounds__(128, 2) void gemm_mma_kernel(
    const float* __restrict__ A, const float* __restrict__ Bw,
    const float* __restrict__ bias, float* __restrict__ C,
    int M, int N, int K)
{
    extern __shared__ float smem[];
    const uint32_t sbase = smem_u32(smem);

    const int tid  = threadIdx.x;
    const int wid  = tid >> 5;
    const int lane = tid & 31;
    const int gid  = lane >> 2;
    const int tig  = lane & 3;

    const int m0 = blockIdx.y * 128;
    const int n0 = blockIdx.x * 128;
    const int wm0 = (wid >> 1) * 64;
    const int wn0 = (wid & 1) * 64;

    float acc[4][8][4];
#pragma unroll
    for (int mi = 0; mi < 4; mi++)
#pragma unroll
        for (int ni = 0; ni < 8; ni++)
#pragma unroll
            for (int r = 0; r < 4; r++) acc[mi][ni][r] = 0.f;

    const int nchunks = K >> 5;

#define GEMM_ISSUE(kc, buf) do {                                              \
    _Pragma("unroll")                                                         \
    for (int i = 0; i < 8; i++) {                                             \
        const int idx = tid + i * 128;                                        \
        const int r  = idx >> 3;                                              \
        const int cg = (idx & 7) << 2;                                        \
        cp_async16(sbase + (uint32_t)(((buf) * GBUF + r * GSTR + cg) * 4),    \
                   A + (size_t)(m0 + r) * K + (kc) + cg);                     \
        cp_async16(sbase + (uint32_t)(((2 + (buf)) * GBUF + r * GSTR + cg) * 4),\
                   Bw + (size_t)(n0 + r) * K + (kc) + cg);                    \
    }                                                                         \
    asm volatile("cp.async.commit_group;" ::: "memory");                      \
} while (0)

    GEMM_ISSUE(0, 0);

    int p = 0;
    for (int c = 0; c < nchunks; c++) {
        const bool more = (c + 1) < nchunks;
        if (more) {
            GEMM_ISSUE((c + 1) << 5, p ^ 1);
            asm volatile("cp.async.wait_group 1;" ::: "memory");
        } else {
            asm volatile("cp.async.wait_group 0;" ::: "memory");
        }
        __syncthreads();

        const float* Ab = smem + p * GBUF;
        const float* Bb = smem + (2 + p) * GBUF;
#pragma unroll
        for (int ks = 0; ks < 4; ks++) {
            const int kk = ks * 8;
            float afr[4][4];
#pragma unroll
            for (int mi = 0; mi < 4; mi++) {
                const int r = wm0 + mi * 16 + gid;
                const int cA = kk + tig;
                afr[mi][0] = Ab[r * GSTR + cA];
                afr[mi][1] = Ab[(r + 8) * GSTR + cA];
                afr[mi][2] = Ab[r * GSTR + cA + 4];
                afr[mi][3] = Ab[(r + 8) * GSTR + cA + 4];
            }
            float bfr[8][2];
#pragma unroll
            for (int ni = 0; ni < 8; ni++) {
                const int rB = wn0 + ni * 8 + gid;
                const int cB = kk + tig;
                bfr[ni][0] = Bb[rB * GSTR + cB];
                bfr[ni][1] = Bb[rB * GSTR + cB + 4];
            }
#pragma unroll
            for (int ni = 0; ni < 8; ni++) {
#pragma unroll
                for (int mi = 0; mi < 4; mi++) {
                    mma_tf32_16x8x8(acc[mi][ni][0], acc[mi][ni][1],
                                    acc[mi][ni][2], acc[mi][ni][3],
                                    afr[mi][0], afr[mi][1], afr[mi][2], afr[mi][3],
                                    bfr[ni][0], bfr[ni][1]);
                }
            }
        }
        __syncthreads();   // all warps done with buf p before refilling it
        p ^= 1;
    }

#pragma unroll
    for (int mi = 0; mi < 4; mi++) {
        const int row = m0 + wm0 + mi * 16 + gid;
#pragma unroll
        for (int ni = 0; ni < 8; ni++) {
            const int col = n0 + wn0 + ni * 8 + 2 * tig;
            float b0 = 0.f, b1 = 0.f;
            if (bias) { b0 = bias[col]; b1 = bias[col + 1]; }
            float2 v0 = make_float2(acc[mi][ni][0] + b0, acc[mi][ni][1] + b1);
            float2 v1 = make_float2(acc[mi][ni][2] + b0, acc[mi][ni][3] + b1);
            *(float2*)(C + (size_t)row * N + col)       = v0;
            *(float2*)(C + (size_t)(row + 8) * N + col) = v1;
        }
    }
}

// ---------------------------------------------------------------------------
// RoPE (in place on g_qkv) + scatter EXACT rotated k and raw v to caches,
// and round q/k/v in qkv to tf32 (so attention loads need no cvt).
// ---------------------------------------------------------------------------
__global__ void rope_scatter_kernel(float* __restrict__ qkv,
                                    const float* __restrict__ cosb,
                                    const float* __restrict__ sinb,
                                    const int* __restrict__ slot,
                                    float* __restrict__ kc,
                                    float* __restrict__ vc) {
    const int r = blockIdx.x;
    float* row = qkv + (size_t)r * NQKV;
    const float* cr = cosb + (size_t)r * Dh;
    const float* sr = sinb + (size_t)r * Dh;
    const int s = slot[r];

    for (int idx = threadIdx.x; idx < 14 * 64; idx += blockDim.x) {
        const int head = idx >> 6;
        const int d = idx & 63;
        float* hp = row + head * Dh;
        const float x1 = hp[d], x2 = hp[d + 64];
        const float c1 = cr[d], s1 = sr[d];
        const float c2 = cr[d + 64], s2 = sr[d + 64];
        const float o1 = x1 * c1 - x2 * s1;
        const float o2 = x2 * c2 + x1 * s2;
        hp[d]      = to_tf32(o1);
        hp[d + 64] = to_tf32(o2);
        if (head >= Hq) {
            const int kh = head - Hq;
            float* kdst = kc + ((size_t)s * HKV + kh) * Dh;
            kdst[d]      = o1;        // cache keeps exact values
            kdst[d + 64] = o2;
        }
    }
    for (int idx = threadIdx.x; idx < HKV * Dh; idx += blockDim.x) {
        const float v = row[Hq * Dh + HKV * Dh + idx];
        vc[(size_t)s * (HKV * Dh) + idx] = v;         // exact
        row[Hq * Dh + HKV * Dh + idx] = to_tf32(v);   // rounded for PV mma
    }
}

// ===========================================================================
// Tensor-core causal GQA flash attention (tf32 mma.sync), cp.async-pipelined.
// R14 config (8 warps 4Mx2N, m32 tiles, exp2f softmax). Changes vs R14:
//  - V(kt) and K(kt+1) in SEPARATE commit groups: pre-PV wait gates only V
//    (wait_group 1); K(kt+1) is waited at the end-of-PV barrier instead,
//    gaining a full PV phase of extra latency cover.
//  - Q prologue load via cp.async (overlaps the K0 wait).
// ===========================================================================
#define AQSTR 132
#define AKSTR 132
#define AVSTR 136
#define ASSTR 68
#define ATT_Q_FL   (128 * AQSTR)
#define ATT_K_FL   (64 * AKSTR)
#define ATT_V_FL   (64 * AVSTR)
#define ATT_S_FL   (128 * ASSTR)
#define ATT2_SMEM_FLOATS (ATT_Q_FL + 2 * ATT_K_FL + ATT_V_FL + ATT_S_FL + 3 * 128)

__global__ __launch_bounds__(256, 1) void attn_mma_kernel(
    const float* __restrict__ qkv, float* __restrict__ out)
{
    extern __shared__ float sm[];
    float* Qs = sm;
    float* Ks0 = Qs + ATT_Q_FL;                 // [2][64][AKSTR]
    float* Vs  = Ks0 + 2 * ATT_K_FL;
    float* Ss  = Vs + ATT_V_FL;
    float* mrow = Ss + ATT_S_FL;
    float* lrow = mrow + 128;
    float* arow = lrow + 128;

    const uint32_t sbase = smem_u32(sm);
    const uint32_t qs_s  = sbase;
    const uint32_t ks_s0 = sbase + (uint32_t)(ATT_Q_FL * 4);
    const uint32_t vs_s  = sbase + (uint32_t)((ATT_Q_FL + 2 * ATT_K_FL) * 4);

    const int qt = (gridDim.x - 1) - blockIdx.x;   // heavy tiles first
    const int h = blockIdx.y, b = blockIdx.z;
    const int kh = h / NG;
    const int tid = threadIdx.x;
    const int wid = tid >> 5;
    const int lane = tid & 31;
    const int gid = lane >> 2;
    const int tig = lane & 3;
    const int wm = wid >> 1;          // 0..3 -> 32-row strip
    const int wn = wid & 1;           // 0..1
    const int q0 = qt * 128;
    const int rowbase = b * Sc;
    // scores scaled by (1/sqrt(128)) * log2(e); softmax uses exp2f.
    const float scale = 0.08838834764831845f * 1.44269504088896340736f;

#define ATT_ISSUE_K(kt_, buf_) do {                                           \
    const uint32_t kb_ = ks_s0 + (uint32_t)((buf_) * ATT_K_FL * 4);           \
    for (int i_ = tid; i_ < 64 * 32; i_ += 256) {                             \
        const int r_ = i_ >> 5; const int c_ = (i_ & 31) << 2;                \
        cp_async16(kb_ + (uint32_t)((r_ * AKSTR + c_) * 4),                   \
                   qkv + (size_t)(rowbase + (kt_) * 64 + r_) * NQKV           \
                       + Hq * Dh + kh * Dh + c_);                             \
    }                                                                         \
} while (0)

#define ATT_ISSUE_V(kt_) do {                                                 \
    for (int i_ = tid; i_ < 64 * 32; i_ += 256) {                             \
        const int r_ = i_ >> 5; const int c_ = (i_ & 31) << 2;                \
        cp_async16(vs_s + (uint32_t)((r_ * AVSTR + c_) * 4),                  \
                   qkv + (size_t)(rowbase + (kt_) * 64 + r_) * NQKV           \
                       + Hq * Dh + HKV * Dh + kh * Dh + c_);                  \
    }                                                                         \
} while (0)

    // --- prologue: prefetch K0 and Q via cp.async, init stats ---
    ATT_ISSUE_K(0, 0);
    for (int i = tid; i < 128 * 32; i += 256) {
        const int r = i >> 5;
        const int c = (i & 31) << 2;
        cp_async16(qs_s + (uint32_t)((r * AQSTR + c) * 4),
                   qkv + (size_t)(rowbase + q0 + r) * NQKV + h * Dh + c);
    }
    asm volatile("cp.async.commit_group;" ::: "memory");

    if (tid < 128) { mrow[tid] = -1e30f; lrow[tid] = 0.f; }

    float oacc[2][8][4];
#pragma unroll
    for (int mi = 0; mi < 2; mi++)
#pragma unroll
        for (int nt = 0; nt < 8; nt++)
#pragma unroll
            for (int r = 0; r < 4; r++) oacc[mi][nt][r] = 0.f;

    asm volatile("cp.async.wait_group 0;" ::: "memory");
    __syncthreads();    // K0 + Q + stats visible

    const int nkt = 2 * qt + 2;
    for (int kt = 0; kt < nkt; kt++) {
        const int k0 = kt * 64;
        const int buf = kt & 1;
        const bool moreK = (kt + 1 < nkt);

        // --- issue V(kt) (own group), then K(kt+1) (own group) ---
        ATT_ISSUE_V(kt);
        asm volatile("cp.async.commit_group;" ::: "memory");
        if (moreK) {
            ATT_ISSUE_K(kt + 1, buf ^ 1);
            asm volatile("cp.async.commit_group;" ::: "memory");
        }

        // --- QK^T from Ks[buf]: warp m32 x n32, k=128 ---
        const float* Kb = Ks0 + buf * ATT_K_FL;
        float sacc[2][4][4];
#pragma unroll
        for (int mi = 0; mi < 2; mi++)
#pragma unroll
            for (int nt = 0; nt < 4; nt++)
#pragma unroll
                for (int r = 0; r < 4; r++) sacc[mi][nt][r] = 0.f;

#pragma unroll
        for (int kk = 0; kk < 16; kk++) {
            const int kc = kk * 8;
            float afr[2][4];
#pragma unroll
            for (int mi = 0; mi < 2; mi++) {
                const int rA = wm * 32 + mi * 16 + gid;
                afr[mi][0] = Qs[rA * AQSTR + kc + tig];
                afr[mi][1] = Qs[(rA + 8) * AQSTR + kc + tig];
                afr[mi][2] = Qs[rA * AQSTR + kc + tig + 4];
                afr[mi][3] = Qs[(rA + 8) * AQSTR + kc + tig + 4];
            }
#pragma unroll
            for (int nt = 0; nt < 4; nt++) {
                const int rB = wn * 32 + nt * 8 + gid;
                const float b0 = Kb[rB * AKSTR + kc + tig];
                const float b1 = Kb[rB * AKSTR + kc + tig + 4];
#pragma unroll
                for (int mi = 0; mi < 2; mi++) {
                    mma_tf32_16x8x8(sacc[mi][nt][0], sacc[mi][nt][1],
                                    sacc[mi][nt][2], sacc[mi][nt][3],
                                    afr[mi][0], afr[mi][1], afr[mi][2], afr[mi][3],
                                    b0, b1);
                }
            }
        }

        // --- scale(+log2e) + causal mask + write scores ---
#pragma unroll
        for (int mi = 0; mi < 2; mi++) {
            const int r0 = wm * 32 + mi * 16 + gid;
            const int r1 = r0 + 8;
            const int qr0 = q0 + r0, qr1 = q0 + r1;
#pragma unroll
            for (int nt = 0; nt < 4; nt++) {
                const int col = wn * 32 + nt * 8 + 2 * tig;
                const int gc = k0 + col;
                Ss[r0 * ASSTR + col]     = (gc     <= qr0) ? sacc[mi][nt][0] * scale : -1e30f;
                Ss[r0 * ASSTR + col + 1] = (gc + 1 <= qr0) ? sacc[mi][nt][1] * scale : -1e30f;
                Ss[r1 * ASSTR + col]     = (gc     <= qr1) ? sacc[mi][nt][2] * scale : -1e30f;
                Ss[r1 * ASSTR + col + 1] = (gc + 1 <= qr1) ? sacc[mi][nt][3] * scale : -1e30f;
            }
        }
        __syncthreads();

        // --- online softmax (base-2): 2 threads/row, interleaved chunks ---
        {
            const int row = tid >> 1;
            const int part = tid & 1;
            float* sp = Ss + row * ASSTR + part * 4;   // chunks at 8j + 4*part
            float4 v[8];
#pragma unroll
            for (int j = 0; j < 8; j++) v[j] = *(float4*)(sp + j * 8);
            float mx = -1e30f;
#pragma unroll
            for (int j = 0; j < 8; j++)
                mx = fmaxf(mx, fmaxf(fmaxf(v[j].x, v[j].y), fmaxf(v[j].z, v[j].w)));
            mx = fmaxf(mx, __shfl_xor_sync(0xFFFFFFFFu, mx, 1));
            const float mo = mrow[row];
            const float mn = fmaxf(mo, mx);
            const float alpha = exp2f(mo - mn);
            float s = 0.f;
#pragma unroll
            for (int j = 0; j < 8; j++) {
                v[j].x = exp2f(v[j].x - mn); v[j].y = exp2f(v[j].y - mn);
                v[j].z = exp2f(v[j].z - mn); v[j].w = exp2f(v[j].w - mn);
                s += (v[j].x + v[j].y) + (v[j].z + v[j].w);
            }
#pragma unroll
            for (int j = 0; j < 8; j++) {
                v[j].x = to_tf32(v[j].x); v[j].y = to_tf32(v[j].y);
                v[j].z = to_tf32(v[j].z); v[j].w = to_tf32(v[j].w);
                *(float4*)(sp + j * 8) = v[j];
            }
            s += __shfl_xor_sync(0xFFFFFFFFu, s, 1);
            if (part == 0) {
                mrow[row] = mn;
                lrow[row] = lrow[row] * alpha + s;
                arow[row] = alpha;
            }
        }
        // Wait for V(kt) ONLY (K(kt+1) group may stay outstanding).
        if (moreK) {
            asm volatile("cp.async.wait_group 1;" ::: "memory");
        } else {
            asm volatile("cp.async.wait_group 0;" ::: "memory");
        }
        __syncthreads();

        // --- rescale O accumulators and P @ V (warp m32 x n64) ---
        {
            float al[2][2];
#pragma unroll
            for (int mi = 0; mi < 2; mi++) {
                al[mi][0] = arow[wm * 32 + mi * 16 + gid];
                al[mi][1] = arow[wm * 32 + mi * 16 + gid + 8];
            }
#pragma unroll
            for (int mi = 0; mi < 2; mi++)
#pragma unroll
                for (int nt = 0; nt < 8; nt++) {
                    oacc[mi][nt][0] *= al[mi][0]; oacc[mi][nt][1] *= al[mi][0];
                    oacc[mi][nt][2] *= al[mi][1]; oacc[mi][nt][3] *= al[mi][1];
                }
#pragma unroll
            for (int ks = 0; ks < 8; ks++) {
                const int kc = ks * 8;
                float pfr[2][4];
#pragma unroll
                for (int mi = 0; mi < 2; mi++) {
                    const int rA = wm * 32 + mi * 16 + gid;
                    pfr[mi][0] = Ss[rA * ASSTR + kc + tig];
                    pfr[mi][1] = Ss[(rA + 8) * ASSTR + kc + tig];
                    pfr[mi][2] = Ss[rA * ASSTR + kc + tig + 4];
                    pfr[mi][3] = Ss[(rA + 8) * ASSTR + kc + tig + 4];
                }
#pragma unroll
                for (int nt = 0; nt < 8; nt++) {
                    const int n0 = wn * 64 + nt * 8;
                    const float b0 = Vs[(kc + tig) * AVSTR + n0 + gid];
                    const float b1 = Vs[(kc + tig + 4) * AVSTR + n0 + gid];
#pragma unroll
                    for (int mi = 0; mi < 2; mi++) {
                        mma_tf32_16x8x8(oacc[mi][nt][0], oacc[mi][nt][1],
                                        oacc[mi][nt][2], oacc[mi][nt][3],
                                        pfr[mi][0], pfr[mi][1], pfr[mi][2], pfr[mi][3],
                                        b0, b1);
                    }
                }
            }
        }
        // K(kt+1) must be landed before next iteration's QK; fold its wait
        // into the existing end-of-PV barrier.
        if (moreK) {
            asm volatile("cp.async.wait_group 0;" ::: "memory");
        }
        __syncthreads();   // protect Vs/Ss + publish K(kt+1)
    }

    // --- normalize + write out (tf32-rounded for the out-projection) ---
#pragma unroll
    for (int mi = 0; mi < 2; mi++) {
        const int r0 = wm * 32 + mi * 16 + gid;
        const int r1 = r0 + 8;
        const float inv0 = 1.0f / lrow[r0];
        const float inv1 = 1.0f / lrow[r1];
        const size_t ob0 = (size_t)(rowbase + q0 + r0) * HID + h * Dh;
        const size_t ob1 = (size_t)(rowbase + q0 + r1) * HID + h * Dh;
#pragma unroll
        for (int nt = 0; nt < 8; nt++) {
            const int col = wn * 64 + nt * 8 + 2 * tig;
            *(float2*)(out + ob0 + col) =
                make_float2(to_tf32(oacc[mi][nt][0] * inv0), to_tf32(oacc[mi][nt][1] * inv0));
            *(float2*)(out + ob1 + col) =
                make_float2(to_tf32(oacc[mi][nt][2] * inv1), to_tf32(oacc[mi][nt][3] * inv1));
        }
    }
}

// ---------------------------------------------------------------------------
// kernel_launch
// ---------------------------------------------------------------------------
extern "C" void kernel_launch(void* const* d_in, const int* in_sizes, int n_in,
                              void* d_out, int out_size) {
    const float* x    = (const float*)d_in[0];
    const float* cosb = (const float*)d_in[1];
    const float* sinb = (const float*)d_in[2];
    const float* kci  = (const float*)d_in[3];
    const float* vci  = (const float*)d_in[4];
    const int*   slot = (const int*)d_in[5];
    const float* Wqkv = (const float*)d_in[6];
    const float* bqkv = (const float*)d_in[7];
    const float* Wo   = (const float*)d_in[8];

    float* out = (float*)d_out;
    float* kc  = out + OUT_ELEMS;
    float* vc  = kc + CACHE_ELEMS;

    float* qkv;  cudaGetSymbolAddress((void**)&qkv,  g_qkv);
    float* attn; cudaGetSymbolAddress((void**)&attn, g_attn);
    float* xe;   cudaGetSymbolAddress((void**)&xe,   g_x);
    float* w1e;  cudaGetSymbolAddress((void**)&w1e,  g_w1);
    float* w2e;  cudaGetSymbolAddress((void**)&w2e,  g_w2);

    cudaFuncSetAttribute(attn_mma_kernel,
                         cudaFuncAttributeMaxDynamicSharedMemorySize,
                         ATT2_SMEM_FLOATS * (int)sizeof(float));
    cudaFuncSetAttribute(gemm_mma_kernel,
                         cudaFuncAttributeMaxDynamicSharedMemorySize,
                         G_SMEM_FLOATS * (int)sizeof(float));

    // 1. seed caches with the input caches
    cudaMemcpyAsync(kc, kci, CACHE_ELEMS * sizeof(float), cudaMemcpyDeviceToDevice);
    cudaMemcpyAsync(vc, vci, CACHE_ELEMS * sizeof(float), cudaMemcpyDeviceToDevice);

    // 2. tf32 pre-rounding of GEMM operands
    tf32_round_kernel<<<(Tn * HID / 4 + 255) / 256, 256>>>(x,    xe,  Tn * HID / 4);
    tf32_round_kernel<<<(NQKV * HID / 4 + 255) / 256, 256>>>(Wqkv, w1e, NQKV * HID / 4);
    tf32_round_kernel<<<(HID * HID / 4 + 255) / 256, 256>>>(Wo,   w2e, HID * HID / 4);

    // 3. QKV projection (2-stage cp.async tf32 mma GEMM, R14 config)
    {
        dim3 grid(NQKV / 128, Tn / 128);
        gemm_mma_kernel<<<grid, 128, G_SMEM_FLOATS * sizeof(float)>>>(
            xe, w1e, bqkv, qkv, Tn, NQKV, HID);
    }

    // 4. RoPE in place (+tf32 rounding) + exact cache scatter
    rope_scatter_kernel<<<Tn, 256>>>(qkv, cosb, sinb, slot, kc, vc);

    // 5. causal GQA flash attention (split V/K commit groups)
    {
        dim3 grid(Sc / 128, Hq, Bc);
        attn_mma_kernel<<<grid, 256, ATT2_SMEM_FLOATS * sizeof(float)>>>(qkv, attn);
    }

    // 6. output projection (2-stage cp.async tf32 mma GEMM, R14 config)
    {
        dim3 grid(HID / 128, Tn / 128);
        gemm_mma_kernel<<<grid, 128, G_SMEM_FLOATS * sizeof(float)>>>(
            attn, w2e, nullptr, out, Tn, HID, HID);
    }
}

// round 17
// speedup vs baseline: 1.0731x; 1.0363x over previous
#include <cuda_runtime.h>
#include <cuda_bf16.h>
#include <cstdint>
#include <math.h>

// Problem constants
#define Hq    12
#define HKV   2
#define NG    6          // Hq / HKV
#define Dh    128
#define HID   1536
#define Bc    4
#define Sc    2048
#define Tn    (Bc*Sc)    // 8192 tokens
#define NQKV  2048       // Hq*Dh + 2*HKV*Dh
#define NSLOTS 16384
#define OUT_ELEMS   ((size_t)Tn*HID)          // 12582912
#define CACHE_ELEMS ((size_t)NSLOTS*HKV*Dh)   // 4194304

// Scratch (device globals; no runtime allocation allowed)
__device__ float g_qkv[(size_t)Tn * NQKV];    // 67 MB
__device__ float g_attn[(size_t)Tn * HID];    // 50 MB (tf32-rounded by attn)
__device__ float g_x [(size_t)Tn * HID];      // tf32-rounded x
__device__ float g_w1[(size_t)NQKV * HID];    // tf32-rounded Wqkv
__device__ float g_w2[(size_t)HID * HID];     // tf32-rounded Wo

// ===========================================================================
// Helpers (portable to plain sm_103 target)
// ===========================================================================
__device__ __forceinline__ float to_tf32(float x) {
    float y;
    asm("cvt.rna.tf32.f32 %0, %1;" : "=f"(y) : "f"(x));
    return y;
}

__device__ __forceinline__ uint32_t smem_u32(const void* p) {
    uint32_t a;
    asm("{ .reg .u64 t; cvta.to.shared.u64 t, %1; cvt.u32.u64 %0, t; }"
        : "=r"(a) : "l"(p));
    return a;
}

__device__ __forceinline__ void cp_async16(uint32_t saddr, const void* g) {
    asm volatile("cp.async.cg.shared.global [%0], [%1], 16;"
                 :: "r"(saddr), "l"(g) : "memory");
}

__device__ __forceinline__ void mma_tf32_16x8x8(
    float& d0, float& d1, float& d2, float& d3,
    float a0, float a1, float a2, float a3,
    float b0, float b1)
{
    uint32_t A0 = __float_as_uint(a0), A1 = __float_as_uint(a1);
    uint32_t A2 = __float_as_uint(a2), A3 = __float_as_uint(a3);
    uint32_t B0 = __float_as_uint(b0), B1 = __float_as_uint(b1);
    asm volatile(
        "mma.sync.aligned.m16n8k8.row.col.f32.tf32.tf32.f32 "
        "{%0,%1,%2,%3}, {%4,%5,%6,%7}, {%8,%9}, {%0,%1,%2,%3};"
        : "+f"(d0), "+f"(d1), "+f"(d2), "+f"(d3)
        : "r"(A0), "r"(A1), "r"(A2), "r"(A3), "r"(B0), "r"(B1));
}

// ---------------------------------------------------------------------------
// Pre-pass: round fp32 buffer to tf32 (rna) into scratch.
// ---------------------------------------------------------------------------
__global__ void tf32_round_kernel(const float* __restrict__ in,
                                  float* __restrict__ out, int n4) {
    const int i = blockIdx.x * blockDim.x + threadIdx.x;
    if (i < n4) {
        float4 v = ((const float4*)in)[i];
        v.x = to_tf32(v.x); v.y = to_tf32(v.y);
        v.z = to_tf32(v.z); v.w = to_tf32(v.w);
        ((float4*)out)[i] = v;
    }
}

// ===========================================================================
// TF32 tensor-core GEMM (R14/R16-validated): 128x128 tile, 4 warps (2Mx2N),
// 64x64 warp tile, 2-stage cp.async ring, stride-36 fragments. FROZEN.
// ===========================================================================
#define GSTR 36
#define GBUF (128 * GSTR)
#define G_SMEM_FLOATS (4 * GBUF)                // A[2] | B[2] = 73728 B

__global__ __launch_bounds__(128, 2) void gemm_mma_kernel(
    const float* __restrict__ A, const float* __restrict__ Bw,
    const float* __restrict__ bias, float* __restrict__ C,
    int M, int N, int K)
{
    extern __shared__ float smem[];
    const uint32_t sbase = smem_u32(smem);

    const int tid  = threadIdx.x;
    const int wid  = tid >> 5;
    const int lane = tid & 31;
    const int gid  = lane >> 2;
    const int tig  = lane & 3;

    const int m0 = blockIdx.y * 128;
    const int n0 = blockIdx.x * 128;
    const int wm0 = (wid >> 1) * 64;
    const int wn0 = (wid & 1) * 64;

    float acc[4][8][4];
#pragma unroll
    for (int mi = 0; mi < 4; mi++)
#pragma unroll
        for (int ni = 0; ni < 8; ni++)
#pragma unroll
            for (int r = 0; r < 4; r++) acc[mi][ni][r] = 0.f;

    const int nchunks = K >> 5;

#define GEMM_ISSUE(kc, buf) do {                                              \
    _Pragma("unroll")                                                         \
    for (int i = 0; i < 8; i++) {                                             \
        const int idx = tid + i * 128;                                        \
        const int r  = idx >> 3;                                              \
        const int cg = (idx & 7) << 2;                                        \
        cp_async16(sbase + (uint32_t)(((buf) * GBUF + r * GSTR + cg) * 4),    \
                   A + (size_t)(m0 + r) * K + (kc) + cg);                     \
        cp_async16(sbase + (uint32_t)(((2 + (buf)) * GBUF + r * GSTR + cg) * 4),\
                   Bw + (size_t)(n0 + r) * K + (kc) + cg);                    \
    }                                                                         \
    asm volatile("cp.async.commit_group;" ::: "memory");                      \
} while (0)

    GEMM_ISSUE(0, 0);

    int p = 0;
    for (int c = 0; c < nchunks; c++) {
        const bool more = (c + 1) < nchunks;
        if (more) {
            GEMM_ISSUE((c + 1) << 5, p ^ 1);
            asm volatile("cp.async.wait_group 1;" ::: "memory");
        } else {
            asm volatile("cp.async.wait_group 0;" ::: "memory");
        }
        __syncthreads();

        const float* Ab = smem + p * GBUF;
        const float* Bb = smem + (2 + p) * GBUF;
#pragma unroll
        for (int ks = 0; ks < 4; ks++) {
            const int kk = ks * 8;
            float afr[4][4];
#pragma unroll
            for (int mi = 0; mi < 4; mi++) {
                const int r = wm0 + mi * 16 + gid;
                const int cA = kk + tig;
                afr[mi][0] = Ab[r * GSTR + cA];
                afr[mi][1] = Ab[(r + 8) * GSTR + cA];
                afr[mi][2] = Ab[r * GSTR + cA + 4];
                afr[mi][3] = Ab[(r + 8) * GSTR + cA + 4];
            }
            float bfr[8][2];
#pragma unroll
            for (int ni = 0; ni < 8; ni++) {
                const int rB = wn0 + ni * 8 + gid;
                const int cB = kk + tig;
                bfr[ni][0] = Bb[rB * GSTR + cB];
                bfr[ni][1] = Bb[rB * GSTR + cB + 4];
            }
#pragma unroll
            for (int ni = 0; ni < 8; ni++) {
#pragma unroll
                for (int mi = 0; mi < 4; mi++) {
                    mma_tf32_16x8x8(acc[mi][ni][0], acc[mi][ni][1],
                                    acc[mi][ni][2], acc[mi][ni][3],
                                    afr[mi][0], afr[mi][1], afr[mi][2], afr[mi][3],
                                    bfr[ni][0], bfr[ni][1]);
                }
            }
        }
        __syncthreads();   // all warps done with buf p before refilling it
        p ^= 1;
    }

#pragma unroll
    for (int mi = 0; mi < 4; mi++) {
        const int row = m0 + wm0 + mi * 16 + gid;
#pragma unroll
        for (int ni = 0; ni < 8; ni++) {
            const int col = n0 + wn0 + ni * 8 + 2 * tig;
            float b0 = 0.f, b1 = 0.f;
            if (bias) { b0 = bias[col]; b1 = bias[col + 1]; }
            float2 v0 = make_float2(acc[mi][ni][0] + b0, acc[mi][ni][1] + b1);
            float2 v1 = make_float2(acc[mi][ni][2] + b0, acc[mi][ni][3] + b1);
            *(float2*)(C + (size_t)row * N + col)       = v0;
            *(float2*)(C + (size_t)(row + 8) * N + col) = v1;
        }
    }
}

// ---------------------------------------------------------------------------
// RoPE (in place on g_qkv) + scatter EXACT rotated k and raw v to caches,
// and round q/k/v in qkv to tf32 (so attention loads need no cvt).
// ---------------------------------------------------------------------------
__global__ void rope_scatter_kernel(float* __restrict__ qkv,
                                    const float* __restrict__ cosb,
                                    const float* __restrict__ sinb,
                                    const int* __restrict__ slot,
                                    float* __restrict__ kc,
                                    float* __restrict__ vc) {
    const int r = blockIdx.x;
    float* row = qkv + (size_t)r * NQKV;
    const float* cr = cosb + (size_t)r * Dh;
    const float* sr = sinb + (size_t)r * Dh;
    const int s = slot[r];

    for (int idx = threadIdx.x; idx < 14 * 64; idx += blockDim.x) {
        const int head = idx >> 6;
        const int d = idx & 63;
        float* hp = row + head * Dh;
        const float x1 = hp[d], x2 = hp[d + 64];
        const float c1 = cr[d], s1 = sr[d];
        const float c2 = cr[d + 64], s2 = sr[d + 64];
        const float o1 = x1 * c1 - x2 * s1;
        const float o2 = x2 * c2 + x1 * s2;
        hp[d]      = to_tf32(o1);
        hp[d + 64] = to_tf32(o2);
        if (head >= Hq) {
            const int kh = head - Hq;
            float* kdst = kc + ((size_t)s * HKV + kh) * Dh;
            kdst[d]      = o1;        // cache keeps exact values
            kdst[d + 64] = o2;
        }
    }
    for (int idx = threadIdx.x; idx < HKV * Dh; idx += blockDim.x) {
        const float v = row[Hq * Dh + HKV * Dh + idx];
        vc[(size_t)s * (HKV * Dh) + idx] = v;         // exact
        row[Hq * Dh + HKV * Dh + idx] = to_tf32(v);   // rounded for PV mma
    }
}

// ===========================================================================
// Tensor-core causal GQA flash attention (tf32 mma.sync), cp.async-pipelined.
// R16 async schedule (split V/K groups, cp.async Q prologue) + NEW:
// register-resident softmax. Scores stay in sacc regs; only per-row partial
// max / partial sum (2 floats/row each) go through smem; P is written to Ss
// exactly once (same layout as before -> PV path unchanged). Running m/l
// live in registers, duplicated across the 8 threads sharing each row
// (identical deterministic computation). Barrier structure identical to R16.
// ===========================================================================
#define AQSTR 132
#define AKSTR 132
#define AVSTR 136
#define ASSTR 68
#define ATT_Q_FL   (128 * AQSTR)
#define ATT_K_FL   (64 * AKSTR)
#define ATT_V_FL   (64 * AVSTR)
#define ATT_S_FL   (128 * ASSTR)
#define ATT2_SMEM_FLOATS (ATT_Q_FL + 2 * ATT_K_FL + ATT_V_FL + ATT_S_FL + 4 * 128)

__global__ __launch_bounds__(256, 1) void attn_mma_kernel(
    const float* __restrict__ qkv, float* __restrict__ out)
{
    extern __shared__ float sm[];
    float* Qs = sm;
    float* Ks0 = Qs + ATT_Q_FL;                 // [2][64][AKSTR]
    float* Vs  = Ks0 + 2 * ATT_K_FL;
    float* Ss  = Vs + ATT_V_FL;
    float* pmS = Ss + ATT_S_FL;                 // [128][2] partial row max
    float* psS = pmS + 2 * 128;                 // [128][2] partial row sum

    const uint32_t sbase = smem_u32(sm);
    const uint32_t qs_s  = sbase;
    const uint32_t ks_s0 = sbase + (uint32_t)(ATT_Q_FL * 4);
    const uint32_t vs_s  = sbase + (uint32_t)((ATT_Q_FL + 2 * ATT_K_FL) * 4);

    const int qt = (gridDim.x - 1) - blockIdx.x;   // heavy tiles first
    const int h = blockIdx.y, b = blockIdx.z;
    const int kh = h / NG;
    const int tid = threadIdx.x;
    const int wid = tid >> 5;
    const int lane = tid & 31;
    const int gid = lane >> 2;
    const int tig = lane & 3;
    const int wm = wid >> 1;          // 0..3 -> 32-row strip
    const int wn = wid & 1;           // 0..1
    const int q0 = qt * 128;
    const int rowbase = b * Sc;
    // scores scaled by (1/sqrt(128)) * log2(e); softmax uses exp2f.
    const float scale = 0.08838834764831845f * 1.44269504088896340736f;

#define ATT_ISSUE_K(kt_, buf_) do {                                           \
    const uint32_t kb_ = ks_s0 + (uint32_t)((buf_) * ATT_K_FL * 4);           \
    for (int i_ = tid; i_ < 64 * 32; i_ += 256) {                             \
        const int r_ = i_ >> 5; const int c_ = (i_ & 31) << 2;                \
        cp_async16(kb_ + (uint32_t)((r_ * AKSTR + c_) * 4),                   \
                   qkv + (size_t)(rowbase + (kt_) * 64 + r_) * NQKV           \
                       + Hq * Dh + kh * Dh + c_);                             \
    }                                                                         \
} while (0)

#define ATT_ISSUE_V(kt_) do {                                                 \
    for (int i_ = tid; i_ < 64 * 32; i_ += 256) {                             \
        const int r_ = i_ >> 5; const int c_ = (i_ & 31) << 2;                \
        cp_async16(vs_s + (uint32_t)((r_ * AVSTR + c_) * 4),                  \
                   qkv + (size_t)(rowbase + (kt_) * 64 + r_) * NQKV           \
                       + Hq * Dh + HKV * Dh + kh * Dh + c_);                  \
    }                                                                         \
} while (0)

    // --- prologue: prefetch K0 and Q via cp.async ---
    ATT_ISSUE_K(0, 0);
    for (int i = tid; i < 128 * 32; i += 256) {
        const int r = i >> 5;
        const int c = (i & 31) << 2;
        cp_async16(qs_s + (uint32_t)((r * AQSTR + c) * 4),
                   qkv + (size_t)(rowbase + q0 + r) * NQKV + h * Dh + c);
    }
    asm volatile("cp.async.commit_group;" ::: "memory");

    // register-resident running stats: [mi][j] for rows wm*32+mi*16+gid+8j
    float m_run[2][2], l_run[2][2];
#pragma unroll
    for (int mi = 0; mi < 2; mi++)
#pragma unroll
        for (int j = 0; j < 2; j++) { m_run[mi][j] = -1e30f; l_run[mi][j] = 0.f; }

    float oacc[2][8][4];
#pragma unroll
    for (int mi = 0; mi < 2; mi++)
#pragma unroll
        for (int nt = 0; nt < 8; nt++)
#pragma unroll
            for (int r = 0; r < 4; r++) oacc[mi][nt][r] = 0.f;

    asm volatile("cp.async.wait_group 0;" ::: "memory");
    __syncthreads();    // K0 + Q visible

    const int nkt = 2 * qt + 2;
    for (int kt = 0; kt < nkt; kt++) {
        const int k0 = kt * 64;
        const int buf = kt & 1;
        const bool moreK = (kt + 1 < nkt);

        // --- issue V(kt) (own group), then K(kt+1) (own group) ---
        ATT_ISSUE_V(kt);
        asm volatile("cp.async.commit_group;" ::: "memory");
        if (moreK) {
            ATT_ISSUE_K(kt + 1, buf ^ 1);
            asm volatile("cp.async.commit_group;" ::: "memory");
        }

        // --- QK^T from Ks[buf]: warp m32 x n32, k=128 ---
        const float* Kb = Ks0 + buf * ATT_K_FL;
        float sacc[2][4][4];
#pragma unroll
        for (int mi = 0; mi < 2; mi++)
#pragma unroll
            for (int nt = 0; nt < 4; nt++)
#pragma unroll
                for (int r = 0; r < 4; r++) sacc[mi][nt][r] = 0.f;

#pragma unroll
        for (int kk = 0; kk < 16; kk++) {
            const int kc = kk * 8;
            float afr[2][4];
#pragma unroll
            for (int mi = 0; mi < 2; mi++) {
                const int rA = wm * 32 + mi * 16 + gid;
                afr[mi][0] = Qs[rA * AQSTR + kc + tig];
                afr[mi][1] = Qs[(rA + 8) * AQSTR + kc + tig];
                afr[mi][2] = Qs[rA * AQSTR + kc + tig + 4];
                afr[mi][3] = Qs[(rA + 8) * AQSTR + kc + tig + 4];
            }
#pragma unroll
            for (int nt = 0; nt < 4; nt++) {
                const int rB = wn * 32 + nt * 8 + gid;
                const float b0 = Kb[rB * AKSTR + kc + tig];
                const float b1 = Kb[rB * AKSTR + kc + tig + 4];
#pragma unroll
                for (int mi = 0; mi < 2; mi++) {
                    mma_tf32_16x8x8(sacc[mi][nt][0], sacc[mi][nt][1],
                                    sacc[mi][nt][2], sacc[mi][nt][3],
                                    afr[mi][0], afr[mi][1], afr[mi][2], afr[mi][3],
                                    b0, b1);
                }
            }
        }

        // --- mask + scale IN REGISTERS; per-warp half-row max; exchange ---
        float pmax[2][2];
#pragma unroll
        for (int mi = 0; mi < 2; mi++) {
            const int r0 = wm * 32 + mi * 16 + gid;
            const int qr0 = q0 + r0, qr1 = qr0 + 8;
            float mx0 = -1e30f, mx1 = -1e30f;
#pragma unroll
            for (int nt = 0; nt < 4; nt++) {
                const int col = wn * 32 + nt * 8 + 2 * tig;
                const int gc = k0 + col;
                sacc[mi][nt][0] = (gc     <= qr0) ? sacc[mi][nt][0] * scale : -1e30f;
                sacc[mi][nt][1] = (gc + 1 <= qr0) ? sacc[mi][nt][1] * scale : -1e30f;
                sacc[mi][nt][2] = (gc     <= qr1) ? sacc[mi][nt][2] * scale : -1e30f;
                sacc[mi][nt][3] = (gc + 1 <= qr1) ? sacc[mi][nt][3] * scale : -1e30f;
                mx0 = fmaxf(mx0, fmaxf(sacc[mi][nt][0], sacc[mi][nt][1]));
                mx1 = fmaxf(mx1, fmaxf(sacc[mi][nt][2], sacc[mi][nt][3]));
            }
            mx0 = fmaxf(mx0, __shfl_xor_sync(0xFFFFFFFFu, mx0, 1));
            mx0 = fmaxf(mx0, __shfl_xor_sync(0xFFFFFFFFu, mx0, 2));
            mx1 = fmaxf(mx1, __shfl_xor_sync(0xFFFFFFFFu, mx1, 1));
            mx1 = fmaxf(mx1, __shfl_xor_sync(0xFFFFFFFFu, mx1, 2));
            pmax[mi][0] = mx0; pmax[mi][1] = mx1;
            if (tig == 0) {
                pmS[r0 * 2 + wn]       = mx0;
                pmS[(r0 + 8) * 2 + wn] = mx1;
            }
        }
        __syncthreads();   // barrier 1: partial maxima visible

        // --- combine max (redundant per row-sharing threads), exp, P, sums ---
        float alpha[2][2], hs[2][2];
#pragma unroll
        for (int mi = 0; mi < 2; mi++) {
            const int r0 = wm * 32 + mi * 16 + gid;
#pragma unroll
            for (int j = 0; j < 2; j++) {
                const int row = r0 + 8 * j;
                const float pm = fmaxf(pmS[row * 2], pmS[row * 2 + 1]);
                const float mn = fmaxf(m_run[mi][j], pm);
                alpha[mi][j] = exp2f(m_run[mi][j] - mn);
                m_run[mi][j] = mn;
                hs[mi][j] = 0.f;
            }
#pragma unroll
            for (int nt = 0; nt < 4; nt++) {
                sacc[mi][nt][0] = exp2f(sacc[mi][nt][0] - m_run[mi][0]);
                sacc[mi][nt][1] = exp2f(sacc[mi][nt][1] - m_run[mi][0]);
                sacc[mi][nt][2] = exp2f(sacc[mi][nt][2] - m_run[mi][1]);
                sacc[mi][nt][3] = exp2f(sacc[mi][nt][3] - m_run[mi][1]);
                hs[mi][0] += sacc[mi][nt][0] + sacc[mi][nt][1];
                hs[mi][1] += sacc[mi][nt][2] + sacc[mi][nt][3];
            }
            hs[mi][0] += __shfl_xor_sync(0xFFFFFFFFu, hs[mi][0], 1);
            hs[mi][0] += __shfl_xor_sync(0xFFFFFFFFu, hs[mi][0], 2);
            hs[mi][1] += __shfl_xor_sync(0xFFFFFFFFu, hs[mi][1], 1);
            hs[mi][1] += __shfl_xor_sync(0xFFFFFFFFu, hs[mi][1], 2);
            // write P (tf32) once, same layout as before
            const int r1 = r0 + 8;
#pragma unroll
            for (int nt = 0; nt < 4; nt++) {
                const int col = wn * 32 + nt * 8 + 2 * tig;
                Ss[r0 * ASSTR + col]     = to_tf32(sacc[mi][nt][0]);
                Ss[r0 * ASSTR + col + 1] = to_tf32(sacc[mi][nt][1]);
                Ss[r1 * ASSTR + col]     = to_tf32(sacc[mi][nt][2]);
                Ss[r1 * ASSTR + col + 1] = to_tf32(sacc[mi][nt][3]);
            }
            if (tig == 0) {
                psS[r0 * 2 + wn] = hs[mi][0];
                psS[r1 * 2 + wn] = hs[mi][1];
            }
        }
        // Wait for V(kt) ONLY (K(kt+1) group may stay outstanding).
        if (moreK) {
            asm volatile("cp.async.wait_group 1;" ::: "memory");
        } else {
            asm volatile("cp.async.wait_group 0;" ::: "memory");
        }
        __syncthreads();   // barrier 2: P + partial sums + V visible

        // --- l update (registers) + rescale O + P @ V (warp m32 x n64) ---
#pragma unroll
        for (int mi = 0; mi < 2; mi++) {
            const int r0 = wm * 32 + mi * 16 + gid;
#pragma unroll
            for (int j = 0; j < 2; j++) {
                const int row = r0 + 8 * j;
                l_run[mi][j] = l_run[mi][j] * alpha[mi][j]
                             + psS[row * 2] + psS[row * 2 + 1];
            }
#pragma unroll
            for (int nt = 0; nt < 8; nt++) {
                oacc[mi][nt][0] *= alpha[mi][0]; oacc[mi][nt][1] *= alpha[mi][0];
                oacc[mi][nt][2] *= alpha[mi][1]; oacc[mi][nt][3] *= alpha[mi][1];
            }
        }
#pragma unroll
        for (int ks = 0; ks < 8; ks++) {
            const int kc = ks * 8;
            float pfr[2][4];
#pragma unroll
            for (int mi = 0; mi < 2; mi++) {
                const int rA = wm * 32 + mi * 16 + gid;
                pfr[mi][0] = Ss[rA * ASSTR + kc + tig];
                pfr[mi][1] = Ss[(rA + 8) * ASSTR + kc + tig];
                pfr[mi][2] = Ss[rA * ASSTR + kc + tig + 4];
                pfr[mi][3] = Ss[(rA + 8) * ASSTR + kc + tig + 4];
            }
#pragma unroll
            for (int nt = 0; nt < 8; nt++) {
                const int n0 = wn * 64 + nt * 8;
                const float b0 = Vs[(kc + tig) * AVSTR + n0 + gid];
                const float b1 = Vs[(kc + tig + 4) * AVSTR + n0 + gid];
#pragma unroll
                for (int mi = 0; mi < 2; mi++) {
                    mma_tf32_16x8x8(oacc[mi][nt][0], oacc[mi][nt][1],
                                    oacc[mi][nt][2], oacc[mi][nt][3],
                                    pfr[mi][0], pfr[mi][1], pfr[mi][2], pfr[mi][3],
                                    b0, b1);
                }
            }
        }
        // K(kt+1) must land before next iteration's QK.
        if (moreK) {
            asm volatile("cp.async.wait_group 0;" ::: "memory");
        }
        __syncthreads();   // barrier 3: protect Vs/Ss + publish K(kt+1)
    }

    // --- normalize + write out (tf32-rounded for the out-projection) ---
#pragma unroll
    for (int mi = 0; mi < 2; mi++) {
        const int r0 = wm * 32 + mi * 16 + gid;
        const int r1 = r0 + 8;
        const float inv0 = 1.0f / l_run[mi][0];
        const float inv1 = 1.0f / l_run[mi][1];
        const size_t ob0 = (size_t)(rowbase + q0 + r0) * HID + h * Dh;
        const size_t ob1 = (size_t)(rowbase + q0 + r1) * HID + h * Dh;
#pragma unroll
        for (int nt = 0; nt < 8; nt++) {
            const int col = wn * 64 + nt * 8 + 2 * tig;
            *(float2*)(out + ob0 + col) =
                make_float2(to_tf32(oacc[mi][nt][0] * inv0), to_tf32(oacc[mi][nt][1] * inv0));
            *(float2*)(out + ob1 + col) =
                make_float2(to_tf32(oacc[mi][nt][2] * inv1), to_tf32(oacc[mi][nt][3] * inv1));
        }
    }
}

// ---------------------------------------------------------------------------
// kernel_launch
// ---------------------------------------------------------------------------
extern "C" void kernel_launch(void* const* d_in, const int* in_sizes, int n_in,
                              void* d_out, int out_size) {
    const float* x    = (const float*)d_in[0];
    const float* cosb = (const float*)d_in[1];
    const float* sinb = (const float*)d_in[2];
    const float* kci  = (const float*)d_in[3];
    const float* vci  = (const float*)d_in[4];
    const int*   slot = (const int*)d_in[5];
    const float* Wqkv = (const float*)d_in[6];
    const float* bqkv = (const float*)d_in[7];
    const float* Wo   = (const float*)d_in[8];

    float* out = (float*)d_out;
    float* kc  = out + OUT_ELEMS;
    float* vc  = kc + CACHE_ELEMS;

    float* qkv;  cudaGetSymbolAddress((void**)&qkv,  g_qkv);
    float* attn; cudaGetSymbolAddress((void**)&attn, g_attn);
    float* xe;   cudaGetSymbolAddress((void**)&xe,   g_x);
    float* w1e;  cudaGetSymbolAddress((void**)&w1e,  g_w1);
    float* w2e;  cudaGetSymbolAddress((void**)&w2e,  g_w2);

    cudaFuncSetAttribute(attn_mma_kernel,
                         cudaFuncAttributeMaxDynamicSharedMemorySize,
                         ATT2_SMEM_FLOATS * (int)sizeof(float));
    cudaFuncSetAttribute(gemm_mma_kernel,
                         cudaFuncAttributeMaxDynamicSharedMemorySize,
                         G_SMEM_FLOATS * (int)sizeof(float));

    // 1. seed caches with the input caches
    cudaMemcpyAsync(kc, kci, CACHE_ELEMS * sizeof(float), cudaMemcpyDeviceToDevice);
    cudaMemcpyAsync(vc, vci, CACHE_ELEMS * sizeof(float), cudaMemcpyDeviceToDevice);

    // 2. tf32 pre-rounding of GEMM operands
    tf32_round_kernel<<<(Tn * HID / 4 + 255) / 256, 256>>>(x,    xe,  Tn * HID / 4);
    tf32_round_kernel<<<(NQKV * HID / 4 + 255) / 256, 256>>>(Wqkv, w1e, NQKV * HID / 4);
    tf32_round_kernel<<<(HID * HID / 4 + 255) / 256, 256>>>(Wo,   w2e, HID * HID / 4);

    // 3. QKV projection (2-stage cp.async tf32 mma GEMM)
    {
        dim3 grid(NQKV / 128, Tn / 128);
        gemm_mma_kernel<<<grid, 128, G_SMEM_FLOATS * sizeof(float)>>>(
            xe, w1e, bqkv, qkv, Tn, NQKV, HID);
    }

    // 4. RoPE in place (+tf32 rounding) + exact cache scatter
    rope_scatter_kernel<<<Tn, 256>>>(qkv, cosb, sinb, slot, kc, vc);

    // 5. causal GQA flash attention (register-resident softmax)
    {
        dim3 grid(Sc / 128, Hq, Bc);
        attn_mma_kernel<<<grid, 256, ATT2_SMEM_FLOATS * sizeof(float)>>>(qkv, attn);
    }

    // 6. output projection (2-stage cp.async tf32 mma GEMM)
    {
        dim3 grid(HID / 128, Tn / 128);
        gemm_mma_kernel<<<grid, 128, G_SMEM_FLOATS * sizeof(float)>>>(
            attn, w2e, nullptr, out, Tn, HID, HID);
    }
}